// round 1
// baseline (speedup 1.0000x reference)
#include <cuda_runtime.h>

// BaseTextureDiffusion: out[b,c,h,w] = sum_{k=0..48} weights[b,c,k,h,w] *
//                       latent_edgepadded[b,c, h+k/7-3, w+k%7-3]
// Shapes: latent (2,24,256,256) f32, weights (2,24,49,256,256) f32, R=7.
//
// Strategy: HBM-bound on the 616MB weights stream. Each thread computes a
// float4 of outputs; weights read as LDG.128 (perfectly coalesced, 49 per
// thread); latent staged in a 10x264 shared tile per block (4 output rows +
// 6 halo rows, 256 cols + halo, edge-clamped), read back as 3x LDS.128 per
// window row with constant-index register windowing for the 7 j-shifts.

#define BB 2
#define CC 24
#define HH 256
#define WW 256
#define RR 7
#define PAD 3
#define HW (HH * WW)

#define TILE_ROWS 4            // output rows per block
#define SROWS (TILE_ROWS + 2 * PAD)   // 10
#define SCOLS 264              // 256 + 8 (cols -4..259 of latent, see mapping)

__global__ __launch_bounds__(256, 8)
void texdiff_kernel(const float* __restrict__ latent,
                    const float* __restrict__ weights,
                    float* __restrict__ out)
{
    __shared__ float tile[SROWS][SCOLS];

    const int bc = blockIdx.z;                 // 0..47  (b*C + c)
    const int h0 = blockIdx.y * TILE_ROWS;     // first output row of tile
    const int x  = threadIdx.x;                // 0..63 : float4 lane over w
    const int y  = threadIdx.y;                // 0..3  : row within tile
    const int tid = y * 64 + x;                // 0..255

    const float* lat = latent + (long)bc * HW;

    // --- Stage latent tile with edge clamp.
    // tile[r][cix] = latent[clamp(h0 + r - 3), clamp(cix - 4)]
    #pragma unroll
    for (int idx = tid; idx < SROWS * SCOLS; idx += 256) {
        int r   = idx / SCOLS;
        int cix = idx - r * SCOLS;
        int gh  = h0 + r - PAD;
        gh = gh < 0 ? 0 : (gh > HH - 1 ? HH - 1 : gh);
        int gw  = cix - 4;
        gw = gw < 0 ? 0 : (gw > WW - 1 ? WW - 1 : gw);
        tile[r][cix] = lat[gh * WW + gw];
    }
    __syncthreads();

    const int h  = h0 + y;
    const int w0 = 4 * x;

    const float* wbase = weights + (long)bc * (RR * RR) * HW + h * WW + w0;

    float4 acc = make_float4(0.f, 0.f, 0.f, 0.f);

    #pragma unroll
    for (int i = 0; i < RR; i++) {
        // 12 consecutive latent values covering cols w0-3 .. w0+8 (+don't-cares)
        const float4* srow = (const float4*)&tile[y + i][w0];
        float4 a = srow[0];
        float4 b = srow[1];
        float4 c = srow[2];
        float r[12] = { a.x, a.y, a.z, a.w,
                        b.x, b.y, b.z, b.w,
                        c.x, c.y, c.z, c.w };
        #pragma unroll
        for (int j = 0; j < RR; j++) {
            const float4 wv = *(const float4*)(wbase + (long)(i * RR + j) * HW);
            acc.x += wv.x * r[1 + j];
            acc.y += wv.y * r[2 + j];
            acc.z += wv.z * r[3 + j];
            acc.w += wv.w * r[4 + j];
        }
    }

    *(float4*)(out + (long)bc * HW + h * WW + w0) = acc;
}

extern "C" void kernel_launch(void* const* d_in, const int* in_sizes, int n_in,
                              void* d_out, int out_size)
{
    const float* latent  = (const float*)d_in[0];
    const float* weights = (const float*)d_in[1];
    // d_in[2] = window_size (int scalar, always 7 for this problem)
    float* out = (float*)d_out;

    dim3 block(64, TILE_ROWS, 1);
    dim3 grid(1, HH / TILE_ROWS, BB * CC);
    texdiff_kernel<<<grid, block>>>(latent, weights, out);
}

// round 2
// speedup vs baseline: 1.1055x; 1.1055x over previous
#include <cuda_runtime.h>

// BaseTextureDiffusion: out[b,c,h,w] = sum_{k=0..48} weights[b,c,k,h,w] *
//                       latent_edgepadded[b,c, h+k/7-3, w+k%7-3]
// Shapes: latent (2,24,256,256) f32, weights (2,24,49,256,256) f32, R=7.
//
// HBM-bound on the 616MB read-once weights stream.
// R2 changes vs R1 (106.9us, DRAM 81.9%):
//  - __ldcs (evict-first) on weights, __stcs on out: keep L2 for the reused latent.
//  - Batch all 7 weight float4s of a window row into registers before the FMA
//    chain (MLP ~7 outstanding LDG.128 per warp instead of ~2).
//  - __launch_bounds__(256, 6) to give ptxas ~42 regs for the batching.

#define BB 2
#define CC 24
#define HH 256
#define WW 256
#define RR 7
#define PAD 3
#define HW (HH * WW)

#define TILE_ROWS 4                   // output rows per block
#define SROWS (TILE_ROWS + 2 * PAD)   // 10
#define SCOLS 264                     // latent cols -4..259

__global__ __launch_bounds__(256, 6)
void texdiff_kernel(const float* __restrict__ latent,
                    const float* __restrict__ weights,
                    float* __restrict__ out)
{
    __shared__ float tile[SROWS][SCOLS];

    const int bc = blockIdx.z;                 // 0..47  (b*C + c)
    const int h0 = blockIdx.y * TILE_ROWS;     // first output row of tile
    const int x  = threadIdx.x;                // 0..63 : float4 lane over w
    const int y  = threadIdx.y;                // 0..3  : row within tile
    const int tid = y * 64 + x;                // 0..255

    const float* lat = latent + (long)bc * HW;

    // Stage latent tile with edge clamp:
    // tile[r][cix] = latent[clamp(h0 + r - 3), clamp(cix - 4)]
    #pragma unroll
    for (int idx = tid; idx < SROWS * SCOLS; idx += 256) {
        int r   = idx / SCOLS;
        int cix = idx - r * SCOLS;
        int gh  = h0 + r - PAD;
        gh = gh < 0 ? 0 : (gh > HH - 1 ? HH - 1 : gh);
        int gw  = cix - 4;
        gw = gw < 0 ? 0 : (gw > WW - 1 ? WW - 1 : gw);
        tile[r][cix] = lat[gh * WW + gw];
    }
    __syncthreads();

    const int h  = h0 + y;
    const int w0 = 4 * x;

    const float* wbase = weights + (long)bc * (RR * RR) * HW + h * WW + w0;

    float4 acc = make_float4(0.f, 0.f, 0.f, 0.f);

    #pragma unroll
    for (int i = 0; i < RR; i++) {
        // Batch: 7 weight vectors for this window row, streaming loads.
        float4 wv[RR];
        #pragma unroll
        for (int j = 0; j < RR; j++)
            wv[j] = __ldcs((const float4*)(wbase + (long)(i * RR + j) * HW));

        // 12 consecutive latent values covering cols w0-3 .. w0+8
        const float4* srow = (const float4*)&tile[y + i][w0];
        float4 a = srow[0];
        float4 b = srow[1];
        float4 c = srow[2];
        float r[12] = { a.x, a.y, a.z, a.w,
                        b.x, b.y, b.z, b.w,
                        c.x, c.y, c.z, c.w };

        #pragma unroll
        for (int j = 0; j < RR; j++) {
            acc.x += wv[j].x * r[1 + j];
            acc.y += wv[j].y * r[2 + j];
            acc.z += wv[j].z * r[3 + j];
            acc.w += wv[j].w * r[4 + j];
        }
    }

    __stcs((float4*)(out + (long)bc * HW + h * WW + w0), acc);
}

extern "C" void kernel_launch(void* const* d_in, const int* in_sizes, int n_in,
                              void* d_out, int out_size)
{
    const float* latent  = (const float*)d_in[0];
    const float* weights = (const float*)d_in[1];
    // d_in[2] = window_size (int scalar, always 7 here)
    float* out = (float*)d_out;

    dim3 block(64, TILE_ROWS, 1);
    dim3 grid(1, HH / TILE_ROWS, BB * CC);
    texdiff_kernel<<<grid, block>>>(latent, weights, out);
}